// round 1
// baseline (speedup 1.0000x reference)
#include <cuda_runtime.h>
#include <math.h>

#define BATCH 2
#define SEQL  2048
#define DMODEL 768
#define NH    12
#define HD    64
#define KSEL  46          // ceil(sqrt(2048))
#define NKV   1536        // K (768) + V (768) columns of Wqkv
#define NROWS (BATCH*SEQL)
#define WQKV_COLS 2304

// -------- scratch (no allocations allowed) --------
__device__ float g_p1[NROWS];                       // selection prob (class 1)
__device__ int   g_idx[BATCH*KSEL];                 // top-k row indices per batch
__device__ float g_kv[(size_t)NROWS * NKV];         // [row][0:768]=K, [768:1536]=V (per-head h*64+d)
__device__ float g_q[BATCH*KSEL*DMODEL];            // Q at selected rows
__device__ float g_ctx[BATCH*KSEL*DMODEL];          // attention context at selected rows

// ============================================================================
// Kernel 1: selection logits + p1, fused with y = x copy.
// One block (256 thr) per row.
// ============================================================================
__global__ void sel_copy_kernel(const float* __restrict__ x,
                                const float* __restrict__ sel_w,
                                const float* __restrict__ sel_b,
                                const float* __restrict__ temp,
                                float* __restrict__ y) {
    int r = blockIdx.x;
    const float* xr = x + (size_t)r * DMODEL;
    float* yr = y + (size_t)r * DMODEL;
    int tid = threadIdx.x;
    float p0 = 0.f, p1 = 0.f;
    #pragma unroll
    for (int j = tid; j < DMODEL; j += 256) {
        float v = xr[j];
        yr[j] = v;
        float2 w = *(const float2*)&sel_w[2*j];
        p0 = fmaf(v, w.x, p0);
        p1 = fmaf(v, w.y, p1);
    }
    #pragma unroll
    for (int off = 16; off; off >>= 1) {
        p0 += __shfl_down_sync(0xffffffffu, p0, off);
        p1 += __shfl_down_sync(0xffffffffu, p1, off);
    }
    __shared__ float s0[8], s1[8];
    int w = tid >> 5;
    if ((tid & 31) == 0) { s0[w] = p0; s1[w] = p1; }
    __syncthreads();
    if (tid == 0) {
        float a0 = 0.f, a1 = 0.f;
        #pragma unroll
        for (int i = 0; i < 8; i++) { a0 += s0[i]; a1 += s1[i]; }
        a0 += sel_b[0]; a1 += sel_b[1];
        float d = (a1 - a0) / temp[0];
        // softmax over 2 classes == sigmoid of logit diff
        g_p1[r] = 1.0f / (1.0f + expf(-d));
    }
}

// ============================================================================
// Kernel 2: top-KSEL per batch (iterative argmax, lowest-index tie-break to
// match jax.lax.top_k stability). One block per batch.
// ============================================================================
__global__ void topk_kernel() {
    int b = blockIdx.x;
    __shared__ float vals[SEQL];
    __shared__ float rv[256];
    __shared__ int   ri[256];
    int tid = threadIdx.x;
    for (int j = tid; j < SEQL; j += 256) vals[j] = g_p1[b*SEQL + j];
    __syncthreads();
    for (int k = 0; k < KSEL; k++) {
        float bv = -1e30f; int bi = 0;
        for (int j = tid; j < SEQL; j += 256) {
            float v = vals[j];
            if (v > bv) { bv = v; bi = j; }       // ascending scan: strict > keeps lowest idx
        }
        rv[tid] = bv; ri[tid] = bi;
        __syncthreads();
        for (int s = 128; s; s >>= 1) {
            if (tid < s) {
                float ov = rv[tid + s]; int oi = ri[tid + s];
                if (ov > rv[tid] || (ov == rv[tid] && oi < ri[tid])) { rv[tid] = ov; ri[tid] = oi; }
            }
            __syncthreads();
        }
        if (tid == 0) {
            g_idx[b*KSEL + k] = ri[0];
            vals[ri[0]] = -2e30f;
        }
        __syncthreads();
    }
}

// ============================================================================
// Kernel 3: K/V projection GEMM (dominant FLOPs).
// KV[r, n] = sum_k X[r,k] * Wqkv[k, 768+n] + bqkv[768+n]
// M=4096, N=1536, K=768. 64x64x16 smem tiles, 4x4 register micro-tile.
// ============================================================================
__global__ void __launch_bounds__(256) kv_gemm_kernel(const float* __restrict__ X,
                                                      const float* __restrict__ W,
                                                      const float* __restrict__ bias) {
    __shared__ float As[16][64];   // [k][m]
    __shared__ float Bs[16][64];   // [k][n]
    int tid = threadIdx.x;
    int tx = tid & 15, ty = tid >> 4;
    int row0 = blockIdx.y * 64;
    int col0 = blockIdx.x * 64;
    int arow = tid >> 2;
    int acol = (tid & 3) << 2;
    int brow = tid >> 4;
    int bcol = (tid & 15) << 2;
    float acc[4][4];
    #pragma unroll
    for (int i = 0; i < 4; i++)
        #pragma unroll
        for (int j = 0; j < 4; j++) acc[i][j] = 0.f;

    const float* Aptr = X + (size_t)(row0 + arow) * DMODEL;
    const float* Bptr = W + 768 + col0 + bcol;

    for (int k0 = 0; k0 < DMODEL; k0 += 16) {
        float4 av = *(const float4*)(Aptr + k0 + acol);
        As[acol+0][arow] = av.x; As[acol+1][arow] = av.y;
        As[acol+2][arow] = av.z; As[acol+3][arow] = av.w;
        float4 bv = *(const float4*)(Bptr + (size_t)(k0 + brow) * WQKV_COLS);
        *(float4*)&Bs[brow][bcol] = bv;
        __syncthreads();
        #pragma unroll
        for (int kk = 0; kk < 16; kk++) {
            float4 a  = *(const float4*)&As[kk][ty << 2];
            float4 bb = *(const float4*)&Bs[kk][tx << 2];
            acc[0][0] = fmaf(a.x, bb.x, acc[0][0]); acc[0][1] = fmaf(a.x, bb.y, acc[0][1]);
            acc[0][2] = fmaf(a.x, bb.z, acc[0][2]); acc[0][3] = fmaf(a.x, bb.w, acc[0][3]);
            acc[1][0] = fmaf(a.y, bb.x, acc[1][0]); acc[1][1] = fmaf(a.y, bb.y, acc[1][1]);
            acc[1][2] = fmaf(a.y, bb.z, acc[1][2]); acc[1][3] = fmaf(a.y, bb.w, acc[1][3]);
            acc[2][0] = fmaf(a.z, bb.x, acc[2][0]); acc[2][1] = fmaf(a.z, bb.y, acc[2][1]);
            acc[2][2] = fmaf(a.z, bb.z, acc[2][2]); acc[2][3] = fmaf(a.z, bb.w, acc[2][3]);
            acc[3][0] = fmaf(a.w, bb.x, acc[3][0]); acc[3][1] = fmaf(a.w, bb.y, acc[3][1]);
            acc[3][2] = fmaf(a.w, bb.z, acc[3][2]); acc[3][3] = fmaf(a.w, bb.w, acc[3][3]);
        }
        __syncthreads();
    }
    #pragma unroll
    for (int i = 0; i < 4; i++) {
        float* out = g_kv + (size_t)(row0 + (ty << 2) + i) * NKV + col0 + (tx << 2);
        #pragma unroll
        for (int j = 0; j < 4; j++)
            out[j] = acc[i][j] + bias[768 + col0 + (tx << 2) + j];
    }
}

// ============================================================================
// Kernel 4: Q projection only at selected rows. One block per selected row.
// ============================================================================
__global__ void q_gather_kernel(const float* __restrict__ x,
                                const float* __restrict__ W,
                                const float* __restrict__ bias) {
    int blk = blockIdx.x;                  // b*KSEL + i
    int b = blk / KSEL;
    int t = g_idx[blk];
    __shared__ float xs[DMODEL];
    int tid = threadIdx.x;                 // 256
    const float* xr = x + (size_t)(b*SEQL + t) * DMODEL;
    for (int j = tid; j < DMODEL; j += 256) xs[j] = xr[j];
    __syncthreads();
    float a0 = 0.f, a1 = 0.f, a2 = 0.f;
    int n0 = tid, n1 = tid + 256, n2 = tid + 512;
    for (int k = 0; k < DMODEL; k++) {
        float xv = xs[k];
        const float* wr = W + (size_t)k * WQKV_COLS;
        a0 = fmaf(xv, wr[n0], a0);
        a1 = fmaf(xv, wr[n1], a1);
        a2 = fmaf(xv, wr[n2], a2);
    }
    float* qo = g_q + (size_t)blk * DMODEL;
    qo[n0] = a0 + bias[n0];
    qo[n1] = a1 + bias[n1];
    qo[n2] = a2 + bias[n2];
}

// ============================================================================
// Kernel 5: flash-decode attention for one (batch, selected-query, head).
// Two-pass softmax with scores staged in SMEM; per-thread 64-wide V accum.
// ============================================================================
__global__ void __launch_bounds__(128) attn_kernel() {
    int blk = blockIdx.x;
    int h  = blk % NH;
    int qi = (blk / NH) % KSEL;
    int b  = blk / (NH * KSEL);
    int t  = g_idx[b*KSEL + qi];
    __shared__ float qs[HD];
    __shared__ float sc[SEQL];
    __shared__ float redv[4*HD];
    __shared__ float redl[4];
    __shared__ float redm[4];
    __shared__ float mglob;
    int tid = threadIdx.x;
    const float* qptr = g_q + (size_t)(b*KSEL + qi)*DMODEL + h*HD;
    if (tid < HD) qs[tid] = qptr[tid] * 0.125f;   // fold 1/sqrt(64)
    __syncthreads();
    const float* kvb = g_kv + (size_t)b * SEQL * NKV;

    // pass 1: scores + running max
    float m_local = -1e30f;
    for (int s = tid; s <= t; s += 128) {
        const float4* kp = (const float4*)(kvb + (size_t)s*NKV + h*HD);
        float a = 0.f;
        #pragma unroll
        for (int j = 0; j < 16; j++) {
            float4 kk = kp[j];
            float4 qq = *(const float4*)&qs[4*j];
            a = fmaf(qq.x, kk.x, a); a = fmaf(qq.y, kk.y, a);
            a = fmaf(qq.z, kk.z, a); a = fmaf(qq.w, kk.w, a);
        }
        sc[s] = a;
        m_local = fmaxf(m_local, a);
    }
    #pragma unroll
    for (int off = 16; off; off >>= 1)
        m_local = fmaxf(m_local, __shfl_xor_sync(0xffffffffu, m_local, off));
    int w = tid >> 5;
    if ((tid & 31) == 0) redm[w] = m_local;
    __syncthreads();
    if (tid == 0) mglob = fmaxf(fmaxf(redm[0], redm[1]), fmaxf(redm[2], redm[3]));
    __syncthreads();
    float m = mglob;

    // pass 2: exp + weighted V accumulate
    float acc[HD];
    #pragma unroll
    for (int d = 0; d < HD; d++) acc[d] = 0.f;
    float l_local = 0.f;
    for (int s = tid; s <= t; s += 128) {
        float p = __expf(sc[s] - m);
        l_local += p;
        const float4* vp = (const float4*)(kvb + (size_t)s*NKV + DMODEL + h*HD);
        #pragma unroll
        for (int j = 0; j < 16; j++) {
            float4 vv = vp[j];
            acc[4*j+0] = fmaf(p, vv.x, acc[4*j+0]);
            acc[4*j+1] = fmaf(p, vv.y, acc[4*j+1]);
            acc[4*j+2] = fmaf(p, vv.z, acc[4*j+2]);
            acc[4*j+3] = fmaf(p, vv.w, acc[4*j+3]);
        }
    }
    #pragma unroll
    for (int off = 16; off; off >>= 1) {
        l_local += __shfl_xor_sync(0xffffffffu, l_local, off);
        #pragma unroll
        for (int d = 0; d < HD; d++)
            acc[d] += __shfl_xor_sync(0xffffffffu, acc[d], off);
    }
    if ((tid & 31) == 0) {
        redl[w] = l_local;
        #pragma unroll
        for (int d = 0; d < HD; d++) redv[w*HD + d] = acc[d];
    }
    __syncthreads();
    if (tid < HD) {
        float ssum = redv[tid] + redv[HD+tid] + redv[2*HD+tid] + redv[3*HD+tid];
        float lt = redl[0] + redl[1] + redl[2] + redl[3];
        g_ctx[(size_t)(b*KSEL + qi)*DMODEL + h*HD + tid] = ssum / lt;
    }
}

// ============================================================================
// Kernel 6: out projection at selected rows, gate by p1, add into y.
// Top-k indices are distinct per batch -> plain read-modify-write is safe.
// ============================================================================
__global__ void outproj_scatter_kernel(const float* __restrict__ Wout,
                                       const float* __restrict__ bout,
                                       float* __restrict__ y) {
    int blk = blockIdx.x;                  // b*KSEL + i
    int b = blk / KSEL;
    int t = g_idx[blk];
    __shared__ float cs[DMODEL];
    int tid = threadIdx.x;                 // 256
    const float* cr = g_ctx + (size_t)blk * DMODEL;
    for (int j = tid; j < DMODEL; j += 256) cs[j] = cr[j];
    __syncthreads();
    float a0 = 0.f, a1 = 0.f, a2 = 0.f;
    int n0 = tid, n1 = tid + 256, n2 = tid + 512;
    for (int k = 0; k < DMODEL; k++) {
        float cv = cs[k];
        const float* wr = Wout + (size_t)k * DMODEL;
        a0 = fmaf(cv, wr[n0], a0);
        a1 = fmaf(cv, wr[n1], a1);
        a2 = fmaf(cv, wr[n2], a2);
    }
    float p = g_p1[b*SEQL + t];
    float* yr = y + (size_t)(b*SEQL + t) * DMODEL;
    yr[n0] += (a0 + bout[n0]) * p;
    yr[n1] += (a1 + bout[n1]) * p;
    yr[n2] += (a2 + bout[n2]) * p;
}

// ============================================================================
extern "C" void kernel_launch(void* const* d_in, const int* in_sizes, int n_in,
                              void* d_out, int out_size) {
    const float* x     = (const float*)d_in[0];
    const float* Wqkv  = (const float*)d_in[1];
    const float* bqkv  = (const float*)d_in[2];
    const float* sel_w = (const float*)d_in[3];
    const float* sel_b = (const float*)d_in[4];
    const float* out_w = (const float*)d_in[5];
    const float* out_b = (const float*)d_in[6];
    const float* temp  = (const float*)d_in[7];
    float* y = (float*)d_out;

    sel_copy_kernel<<<NROWS, 256>>>(x, sel_w, sel_b, temp, y);
    dim3 g3(NKV/64, NROWS/64);
    kv_gemm_kernel<<<g3, 256>>>(x, Wqkv, bqkv);
    topk_kernel<<<BATCH, 256>>>();
    q_gather_kernel<<<BATCH*KSEL, 256>>>(x, Wqkv, bqkv);
    attn_kernel<<<BATCH*KSEL*NH, 128>>>();
    outproj_scatter_kernel<<<BATCH*KSEL, 256>>>(out_w, out_b, y);
}

// round 2
// speedup vs baseline: 1.7615x; 1.7615x over previous
#include <cuda_runtime.h>
#include <math.h>

#define BATCH 2
#define SEQL  2048
#define DMODEL 768
#define NH    12
#define HD    64
#define KSEL  46          // ceil(sqrt(2048))
#define NKV   1536
#define NROWS (BATCH*SEQL)
#define WQKV_COLS 2304
#define NQ    (BATCH*KSEL)     // 92
#define NQP   96               // padded to 2x48
#define CH    64               // attention key chunk
#define NCH   (SEQL/CH)        // 32

// -------- scratch --------
__device__ float g_p1[NROWS];
__device__ int   g_idx[NQ];
__device__ float g_kv[(size_t)NROWS * NKV];        // [row][0:768]=K, [768:1536]=V
__device__ float g_xq[NQP*DMODEL];                 // gathered x at selected rows (padded)
__device__ float g_q[NQP*DMODEL];                  // Q at selected rows (atomic accum)
__device__ float g_ctx[NQP*DMODEL];                // attention context (pad rows stay 0)
__device__ float g_pm[BATCH*NH*NCH*48];            // per-chunk max
__device__ float g_pl[BATCH*NH*NCH*48];            // per-chunk sum
__device__ float g_po[(size_t)BATCH*NH*NCH*48*HD]; // per-chunk partial output

// ============================================================================
// Kernel 1: selection prob + y = x copy. One block per row.
// ============================================================================
__global__ void sel_copy_kernel(const float* __restrict__ x,
                                const float* __restrict__ sel_w,
                                const float* __restrict__ sel_b,
                                const float* __restrict__ temp,
                                float* __restrict__ y) {
    int r = blockIdx.x;
    const float* xr = x + (size_t)r * DMODEL;
    float* yr = y + (size_t)r * DMODEL;
    int tid = threadIdx.x;
    float p0 = 0.f, p1 = 0.f;
    #pragma unroll
    for (int j = tid; j < DMODEL; j += 256) {
        float v = xr[j];
        yr[j] = v;
        float2 w = *(const float2*)&sel_w[2*j];
        p0 = fmaf(v, w.x, p0);
        p1 = fmaf(v, w.y, p1);
    }
    #pragma unroll
    for (int off = 16; off; off >>= 1) {
        p0 += __shfl_down_sync(0xffffffffu, p0, off);
        p1 += __shfl_down_sync(0xffffffffu, p1, off);
    }
    __shared__ float s0[8], s1[8];
    int w = tid >> 5;
    if ((tid & 31) == 0) { s0[w] = p0; s1[w] = p1; }
    __syncthreads();
    if (tid == 0) {
        float a0 = 0.f, a1 = 0.f;
        #pragma unroll
        for (int i = 0; i < 8; i++) { a0 += s0[i]; a1 += s1[i]; }
        a0 += sel_b[0]; a1 += sel_b[1];
        float d = (a1 - a0) / temp[0];
        g_p1[r] = 1.0f / (1.0f + expf(-d));
    }
}

// ============================================================================
// Kernel 2: warp-only iterative top-KSEL per batch (lowest-index tie-break).
// ============================================================================
__global__ void topk_kernel() {
    int b = blockIdx.x;
    __shared__ float vals[SEQL];
    int tid = threadIdx.x;   // 32
    for (int j = tid; j < SEQL; j += 32) vals[j] = g_p1[b*SEQL + j];
    __syncwarp();
    for (int k = 0; k < KSEL; k++) {
        float bv = -1e30f; int bi = 1 << 30;
        for (int j = tid; j < SEQL; j += 32) {
            float v = vals[j];
            if (v > bv) { bv = v; bi = j; }
        }
        #pragma unroll
        for (int off = 16; off; off >>= 1) {
            float ov = __shfl_xor_sync(0xffffffffu, bv, off);
            int   oi = __shfl_xor_sync(0xffffffffu, bi, off);
            if (ov > bv || (ov == bv && oi < bi)) { bv = ov; bi = oi; }
        }
        if (tid == 0) {
            g_idx[b*KSEL + k] = bi;
            vals[bi] = -2e30f;
        }
        __syncwarp();
    }
}

// ============================================================================
// Kernel 3: gather selected x rows into compact g_xq, zero g_q accumulator.
// ============================================================================
__global__ void gather_kernel(const float* __restrict__ x) {
    int r = blockIdx.x;   // 0..95
    int tid = threadIdx.x; // 256
    float* gq = g_q + (size_t)r * DMODEL;
    float* gx = g_xq + (size_t)r * DMODEL;
    if (r < NQ) {
        int b = r / KSEL;
        int t = g_idx[r];
        const float* xr = x + (size_t)(b*SEQL + t) * DMODEL;
        for (int j = tid; j < DMODEL; j += 256) { gx[j] = xr[j]; gq[j] = 0.f; }
    } else {
        for (int j = tid; j < DMODEL; j += 256) { gx[j] = 0.f; gq[j] = 0.f; }
    }
}

// ============================================================================
// Kernel 4: K/V projection GEMM. M=4096, N=1536, K=768.
// 128x64 tile, 8x4 micro, k-step 16, register double-buffered loads.
// ============================================================================
__global__ void __launch_bounds__(256) kv_gemm_kernel(const float* __restrict__ X,
                                                      const float* __restrict__ W,
                                                      const float* __restrict__ bias) {
    __shared__ float As[16][128];
    __shared__ float Bs[16][64];
    int tid = threadIdx.x;
    int tx = tid & 15, ty = tid >> 4;
    int row0 = blockIdx.y * 128;
    int col0 = blockIdx.x * 64;

    int ar = tid >> 1;
    int ac = (tid & 1) * 8;
    const float* Ap = X + (size_t)(row0 + ar) * DMODEL + ac;
    int bkr = tid >> 4;
    int bcb = (tid & 15) << 2;
    const float* Bp = W + 768 + (size_t)bkr * WQKV_COLS + col0 + bcb;

    float acc[8][4];
    #pragma unroll
    for (int i = 0; i < 8; i++)
        #pragma unroll
        for (int j = 0; j < 4; j++) acc[i][j] = 0.f;

    float4 a0 = *(const float4*)(Ap);
    float4 a1 = *(const float4*)(Ap + 4);
    float4 b0 = *(const float4*)(Bp);

    for (int k0 = 0; k0 < DMODEL; k0 += 16) {
        As[ac+0][ar] = a0.x; As[ac+1][ar] = a0.y; As[ac+2][ar] = a0.z; As[ac+3][ar] = a0.w;
        As[ac+4][ar] = a1.x; As[ac+5][ar] = a1.y; As[ac+6][ar] = a1.z; As[ac+7][ar] = a1.w;
        *(float4*)&Bs[bkr][bcb] = b0;
        __syncthreads();
        if (k0 + 16 < DMODEL) {
            a0 = *(const float4*)(Ap + k0 + 16);
            a1 = *(const float4*)(Ap + k0 + 20);
            b0 = *(const float4*)(Bp + (size_t)(k0 + 16) * WQKV_COLS);
        }
        #pragma unroll
        for (int kk = 0; kk < 16; kk++) {
            float4 av0 = *(const float4*)&As[kk][ty*8];
            float4 av1 = *(const float4*)&As[kk][ty*8+4];
            float4 bv  = *(const float4*)&Bs[kk][tx*4];
            float a[8] = {av0.x,av0.y,av0.z,av0.w,av1.x,av1.y,av1.z,av1.w};
            #pragma unroll
            for (int i = 0; i < 8; i++) {
                acc[i][0] = fmaf(a[i], bv.x, acc[i][0]);
                acc[i][1] = fmaf(a[i], bv.y, acc[i][1]);
                acc[i][2] = fmaf(a[i], bv.z, acc[i][2]);
                acc[i][3] = fmaf(a[i], bv.w, acc[i][3]);
            }
        }
        __syncthreads();
    }
    int colbase = col0 + tx*4;
    float4 bb = *(const float4*)&bias[768 + colbase];
    #pragma unroll
    for (int i = 0; i < 8; i++) {
        int row = row0 + ty*8 + i;
        float4 r;
        r.x = acc[i][0] + bb.x; r.y = acc[i][1] + bb.y;
        r.z = acc[i][2] + bb.z; r.w = acc[i][3] + bb.w;
        *(float4*)&g_kv[(size_t)row * NKV + colbase] = r;
    }
}

// ============================================================================
// Kernel 5: Q projection for selected rows as a k-split GEMM.
// C[96x768] += g_xq[96x768] @ Wqkv[:, 0:768]. Tile 48x64, kchunk 64, 12 splits.
// ============================================================================
__global__ void __launch_bounds__(256) qproj_kernel(const float* __restrict__ W,
                                                    const float* __restrict__ bias) {
    __shared__ float As[64*48];   // [k][row]
    __shared__ float Bs[64*64];   // [k][col]
    int tid = threadIdx.x;
    int tx = tid & 15, ty = tid >> 4;
    int cb = blockIdx.x * 64;
    int rt = blockIdx.y;          // row tile (48 rows)
    int kb = blockIdx.z * 64;

    // load A: 48 rows x 64 k
    #pragma unroll
    for (int l = 0; l < 3; l++) {
        int fid = tid + l*256;
        int row = fid >> 4;
        int kc  = (fid & 15) << 2;
        float4 v = *(const float4*)&g_xq[(size_t)(rt*48 + row)*DMODEL + kb + kc];
        As[(kc+0)*48 + row] = v.x; As[(kc+1)*48 + row] = v.y;
        As[(kc+2)*48 + row] = v.z; As[(kc+3)*48 + row] = v.w;
    }
    // load B: 64 k x 64 cols
    #pragma unroll
    for (int l = 0; l < 4; l++) {
        int fid = tid + l*256;
        int kr = fid >> 4;
        int c4 = (fid & 15) << 2;
        *(float4*)&Bs[kr*64 + c4] = *(const float4*)&W[(size_t)(kb + kr)*WQKV_COLS + cb + c4];
    }
    __syncthreads();
    float acc[3][4];
    #pragma unroll
    for (int i = 0; i < 3; i++)
        #pragma unroll
        for (int j = 0; j < 4; j++) acc[i][j] = 0.f;
    #pragma unroll 8
    for (int k = 0; k < 64; k++) {
        float4 bv = *(const float4*)&Bs[k*64 + tx*4];
        #pragma unroll
        for (int i = 0; i < 3; i++) {
            float a = As[k*48 + ty*3 + i];
            acc[i][0] = fmaf(a, bv.x, acc[i][0]);
            acc[i][1] = fmaf(a, bv.y, acc[i][1]);
            acc[i][2] = fmaf(a, bv.z, acc[i][2]);
            acc[i][3] = fmaf(a, bv.w, acc[i][3]);
        }
    }
    #pragma unroll
    for (int i = 0; i < 3; i++) {
        int row = rt*48 + ty*3 + i;
        if (row < NQ) {
            #pragma unroll
            for (int j = 0; j < 4; j++) {
                int col = cb + tx*4 + j;
                float v = acc[i][j] + (blockIdx.z == 0 ? bias[col] : 0.f);
                atomicAdd(&g_q[(size_t)row*DMODEL + col], v);
            }
        }
    }
}

// ============================================================================
// Kernel 6: flash-decode attention chunk. Block = (chunk, head, batch).
// All 46 queries of the batch share staged K (transposed) and V.
// ============================================================================
__global__ void __launch_bounds__(256) attn_chunk_kernel() {
    int c  = blockIdx.x;      // 0..31
    int h  = blockIdx.y;      // 0..11
    int b  = blockIdx.z;      // 0..1
    int c0 = c * CH;
    int tid = threadIdx.x;
    int tx = tid & 15, ty = tid >> 4;

    __shared__ float qs[48*HD];       // 12 KB, scaled Q
    __shared__ float kv_s[CH*HD];     // 16 KB, Kt [d][key] then Vs [key][d]
    __shared__ float S[48*66];        // ~12.7 KB, padded stride 66
    __shared__ int   ts[48];

    if (tid < 48) ts[tid] = (tid < KSEL) ? g_idx[b*KSEL + tid] : -1;
    // load Q (scaled)
    for (int idx = tid; idx < 48*HD; idx += 256) {
        int q = idx >> 6, d = idx & 63;
        qs[idx] = (q < KSEL) ? g_q[(size_t)(b*KSEL + q)*DMODEL + h*HD + d] * 0.125f : 0.f;
    }
    // load K transposed: Kt[d][key]
    const float* kvb = g_kv + (size_t)b * SEQL * NKV;
    #pragma unroll
    for (int l = 0; l < 4; l++) {
        int fid = tid + l*256;
        int key = fid >> 4;
        int dq  = (fid & 15) << 2;
        float4 v = *(const float4*)&kvb[(size_t)(c0 + key)*NKV + h*HD + dq];
        kv_s[(dq+0)*CH + key] = v.x; kv_s[(dq+1)*CH + key] = v.y;
        kv_s[(dq+2)*CH + key] = v.z; kv_s[(dq+3)*CH + key] = v.w;
    }
    __syncthreads();

    // S = qs @ Kt : 48x64, micro 3x4
    float acc[3][4];
    #pragma unroll
    for (int i = 0; i < 3; i++)
        #pragma unroll
        for (int j = 0; j < 4; j++) acc[i][j] = 0.f;
    #pragma unroll 8
    for (int d = 0; d < HD; d++) {
        float4 bv = *(const float4*)&kv_s[d*CH + tx*4];
        #pragma unroll
        for (int i = 0; i < 3; i++) {
            float a = qs[(ty*3+i)*HD + d];
            acc[i][0] = fmaf(a, bv.x, acc[i][0]);
            acc[i][1] = fmaf(a, bv.y, acc[i][1]);
            acc[i][2] = fmaf(a, bv.z, acc[i][2]);
            acc[i][3] = fmaf(a, bv.w, acc[i][3]);
        }
    }
    #pragma unroll
    for (int i = 0; i < 3; i++) {
        int q = ty*3 + i;
        int tq = ts[q];
        #pragma unroll
        for (int j = 0; j < 4; j++) {
            int sg = c0 + tx*4 + j;
            S[q*66 + tx*4 + j] = (q < KSEL && sg <= tq) ? acc[i][j] : -1e30f;
        }
    }
    __syncthreads();

    // load V (overwrites Kt): Vs[key][d]
    #pragma unroll
    for (int l = 0; l < 4; l++) {
        int fid = tid + l*256;
        int key = fid >> 4;
        int dq  = (fid & 15) << 2;
        *(float4*)&kv_s[key*HD + dq] =
            *(const float4*)&kvb[(size_t)(c0 + key)*NKV + DMODEL + h*HD + dq];
    }
    // softmax per query row (threads 0..47)
    if (tid < 48) {
        int q = tid;
        float m = -1e30f;
        #pragma unroll 8
        for (int k = 0; k < CH; k++) m = fmaxf(m, S[q*66 + k]);
        float l = 0.f;
        #pragma unroll 8
        for (int k = 0; k < CH; k++) {
            float v = S[q*66 + k];
            float p = (v > -1e29f) ? __expf(v - m) : 0.f;
            S[q*66 + k] = p;
            l += p;
        }
        int base = ((b*NH + h)*NCH + c)*48 + q;
        g_pm[base] = m;
        g_pl[base] = l;
    }
    __syncthreads();

    // O = P @ V : 48x64, micro 3x4
    float acc2[3][4];
    #pragma unroll
    for (int i = 0; i < 3; i++)
        #pragma unroll
        for (int j = 0; j < 4; j++) acc2[i][j] = 0.f;
    #pragma unroll 8
    for (int k = 0; k < CH; k++) {
        float4 bv = *(const float4*)&kv_s[k*HD + tx*4];
        #pragma unroll
        for (int i = 0; i < 3; i++) {
            float a = S[(ty*3+i)*66 + k];
            acc2[i][0] = fmaf(a, bv.x, acc2[i][0]);
            acc2[i][1] = fmaf(a, bv.y, acc2[i][1]);
            acc2[i][2] = fmaf(a, bv.z, acc2[i][2]);
            acc2[i][3] = fmaf(a, bv.w, acc2[i][3]);
        }
    }
    size_t obase = ((size_t)((b*NH + h)*NCH + c))*48;
    #pragma unroll
    for (int i = 0; i < 3; i++) {
        float4 r; r.x = acc2[i][0]; r.y = acc2[i][1]; r.z = acc2[i][2]; r.w = acc2[i][3];
        *(float4*)&g_po[(obase + ty*3 + i)*HD + tx*4] = r;
    }
}

// ============================================================================
// Kernel 7: combine chunk partials -> g_ctx. Block per (query, head).
// ============================================================================
__global__ void attn_combine_kernel() {
    int bx = blockIdx.x;     // 0..1103
    int q  = bx / NH;        // compact query 0..91
    int h  = bx % NH;
    int b  = q / KSEL;
    int qi = q % KSEL;
    int d  = threadIdx.x;    // 64
    int bh = b*NH + h;

    float m = -1e30f;
    #pragma unroll
    for (int c = 0; c < NCH; c++)
        m = fmaxf(m, g_pm[(bh*NCH + c)*48 + qi]);
    float num = 0.f, den = 0.f;
    #pragma unroll
    for (int c = 0; c < NCH; c++) {
        int base = (bh*NCH + c)*48 + qi;
        float w = __expf(g_pm[base] - m);
        den = fmaf(w, g_pl[base], den);
        num = fmaf(w, g_po[(size_t)base*HD + d], num);
    }
    g_ctx[(size_t)q*DMODEL + h*HD + d] = num / den;
}

// ============================================================================
// Kernel 8: out projection (k-split GEMM) + gate + scatter-add into y.
// ============================================================================
__global__ void __launch_bounds__(256) outproj_kernel(const float* __restrict__ W,
                                                      const float* __restrict__ bias,
                                                      float* __restrict__ y) {
    __shared__ float As[64*48];
    __shared__ float Bs[64*64];
    int tid = threadIdx.x;
    int tx = tid & 15, ty = tid >> 4;
    int cb = blockIdx.x * 64;
    int rt = blockIdx.y;
    int kb = blockIdx.z * 64;

    #pragma unroll
    for (int l = 0; l < 3; l++) {
        int fid = tid + l*256;
        int row = fid >> 4;
        int kc  = (fid & 15) << 2;
        float4 v = *(const float4*)&g_ctx[(size_t)(rt*48 + row)*DMODEL + kb + kc];
        As[(kc+0)*48 + row] = v.x; As[(kc+1)*48 + row] = v.y;
        As[(kc+2)*48 + row] = v.z; As[(kc+3)*48 + row] = v.w;
    }
    #pragma unroll
    for (int l = 0; l < 4; l++) {
        int fid = tid + l*256;
        int kr = fid >> 4;
        int c4 = (fid & 15) << 2;
        *(float4*)&Bs[kr*64 + c4] = *(const float4*)&W[(size_t)(kb + kr)*DMODEL + cb + c4];
    }
    __syncthreads();
    float acc[3][4];
    #pragma unroll
    for (int i = 0; i < 3; i++)
        #pragma unroll
        for (int j = 0; j < 4; j++) acc[i][j] = 0.f;
    #pragma unroll 8
    for (int k = 0; k < 64; k++) {
        float4 bv = *(const float4*)&Bs[k*64 + tx*4];
        #pragma unroll
        for (int i = 0; i < 3; i++) {
            float a = As[k*48 + ty*3 + i];
            acc[i][0] = fmaf(a, bv.x, acc[i][0]);
            acc[i][1] = fmaf(a, bv.y, acc[i][1]);
            acc[i][2] = fmaf(a, bv.z, acc[i][2]);
            acc[i][3] = fmaf(a, bv.w, acc[i][3]);
        }
    }
    #pragma unroll
    for (int i = 0; i < 3; i++) {
        int row = rt*48 + ty*3 + i;
        if (row < NQ) {
            int b = row / KSEL;
            int t = g_idx[row];
            float p = g_p1[b*SEQL + t];
            float* yr = y + (size_t)(b*SEQL + t)*DMODEL;
            #pragma unroll
            for (int j = 0; j < 4; j++) {
                int col = cb + tx*4 + j;
                float v = acc[i][j] + (blockIdx.z == 0 ? bias[col] : 0.f);
                atomicAdd(&yr[col], p * v);
            }
        }
    }
}

// ============================================================================
extern "C" void kernel_launch(void* const* d_in, const int* in_sizes, int n_in,
                              void* d_out, int out_size) {
    const float* x     = (const float*)d_in[0];
    const float* Wqkv  = (const float*)d_in[1];
    const float* bqkv  = (const float*)d_in[2];
    const float* sel_w = (const float*)d_in[3];
    const float* sel_b = (const float*)d_in[4];
    const float* out_w = (const float*)d_in[5];
    const float* out_b = (const float*)d_in[6];
    const float* temp  = (const float*)d_in[7];
    float* y = (float*)d_out;

    sel_copy_kernel<<<NROWS, 256>>>(x, sel_w, sel_b, temp, y);
    kv_gemm_kernel<<<dim3(NKV/64, NROWS/128), 256>>>(x, Wqkv, bqkv);
    topk_kernel<<<BATCH, 32>>>();
    gather_kernel<<<NQP, 256>>>(x);
    qproj_kernel<<<dim3(12, 2, 12), 256>>>(Wqkv, bqkv);
    attn_chunk_kernel<<<dim3(NCH, NH, BATCH), 256>>>();
    attn_combine_kernel<<<NQ*NH, HD>>>();
    outproj_kernel<<<dim3(12, 2, 12), 256>>>(out_w, out_b, y);
}

// round 4
// speedup vs baseline: 3.8834x; 2.2046x over previous
#include <cuda_runtime.h>
#include <cuda_bf16.h>
#include <math.h>
#include <stdint.h>

#define BATCH 2
#define SEQL  2048
#define DMODEL 768
#define NH    12
#define HD    64
#define KSEL  46
#define NKV   1536
#define NROWS (BATCH*SEQL)
#define WQKV_COLS 2304
#define NQ    (BATCH*KSEL)
#define NQP   96
#define CH    64
#define NCH   (SEQL/CH)

// -------- scratch --------
__device__ float g_p1[NROWS];
__device__ int   g_idx[NQ];
__device__ float g_kv[(size_t)NROWS * NKV];
__device__ float g_xq[NQP*DMODEL];
__device__ float g_q[NQP*DMODEL];
__device__ float g_ctx[NQP*DMODEL];
__device__ float g_pm[BATCH*NH*NCH*48];
__device__ float g_pl[BATCH*NH*NCH*48];
__device__ float g_po[(size_t)BATCH*NH*NCH*48*HD];
__device__ __nv_bfloat16 g_xb[(size_t)NROWS * DMODEL];   // X bf16, row-major [row][k]
__device__ __nv_bfloat16 g_wt[(size_t)NKV * DMODEL];     // W_kv bf16 transposed [n][k]

// ============================================================================
// X fp32 -> bf16
// ============================================================================
__global__ void x_convert_kernel(const float* __restrict__ X) {
    size_t i = ((size_t)blockIdx.x * blockDim.x + threadIdx.x) * 8;
    float4 a = *(const float4*)(X + i);
    float4 b = *(const float4*)(X + i + 4);
    __nv_bfloat16 o[8];
    o[0]=__float2bfloat16(a.x); o[1]=__float2bfloat16(a.y);
    o[2]=__float2bfloat16(a.z); o[3]=__float2bfloat16(a.w);
    o[4]=__float2bfloat16(b.x); o[5]=__float2bfloat16(b.y);
    o[6]=__float2bfloat16(b.z); o[7]=__float2bfloat16(b.w);
    *(uint4*)(g_xb + i) = *(uint4*)o;
}

// ============================================================================
// W_kv (cols 768:2304) -> g_wt[n][k] bf16 (transpose)
// ============================================================================
__global__ void w_transpose_kernel(const float* __restrict__ W) {
    __shared__ float t[32][33];
    int n0 = blockIdx.x * 32;
    int k0 = blockIdx.y * 32;
    int tx = threadIdx.x, ty = threadIdx.y;   // (32, 8)
    #pragma unroll
    for (int i = 0; i < 4; i++)
        t[ty + 8*i][tx] = W[(size_t)(k0 + ty + 8*i) * WQKV_COLS + 768 + n0 + tx];
    __syncthreads();
    #pragma unroll
    for (int i = 0; i < 4; i++)
        g_wt[(size_t)(n0 + ty + 8*i) * DMODEL + k0 + tx] = __float2bfloat16(t[tx][ty + 8*i]);
}

// ============================================================================
// KV GEMM via mma.sync m16n8k16 bf16. C[4096x1536] = Xb @ Wt^T (+bias).
// CTA 128x64, 8 warps (4Mx2N), warp tile 32x32, K-chunk 64.
// ============================================================================
#define SA_STRIDE 72
#define SB_STRIDE 72

__device__ __forceinline__ void mma16816(float* c, const uint32_t* a, const uint32_t* b) {
    asm volatile(
        "mma.sync.aligned.m16n8k16.row.col.f32.bf16.bf16.f32 "
        "{%0,%1,%2,%3}, {%4,%5,%6,%7}, {%8,%9}, {%0,%1,%2,%3};"
        : "+f"(c[0]), "+f"(c[1]), "+f"(c[2]), "+f"(c[3])
        : "r"(a[0]), "r"(a[1]), "r"(a[2]), "r"(a[3]), "r"(b[0]), "r"(b[1]));
}

__global__ void __launch_bounds__(256) kv_mma_kernel(const float* __restrict__ bias) {
    __shared__ __nv_bfloat16 sA[128*SA_STRIDE];   // 18 KB
    __shared__ __nv_bfloat16 sB[64*SB_STRIDE];    // 9 KB
    int tid = threadIdx.x;
    int wid = tid >> 5, lane = tid & 31;
    int wm = wid >> 1, wn = wid & 1;            // warp grid 4x2
    int g = lane >> 2, tg = lane & 3;
    int row0 = blockIdx.y * 128;
    int col0 = blockIdx.x * 64;

    float c[2][4][4];
    #pragma unroll
    for (int mi = 0; mi < 2; mi++)
        #pragma unroll
        for (int ni = 0; ni < 4; ni++)
            #pragma unroll
            for (int j = 0; j < 4; j++) c[mi][ni][j] = 0.f;

    for (int kc = 0; kc < 12; kc++) {
        int k0 = kc * 64;
        // load A chunk: 128 rows x 64 k = 1024 uint4, 4 per thread
        #pragma unroll
        for (int l = 0; l < 4; l++) {
            int fid = tid + l * 256;
            int r = fid >> 3;          // 0..127
            int u = fid & 7;           // 8-elem unit
            uint4 v = *(const uint4*)(g_xb + (size_t)(row0 + r) * DMODEL + k0 + u * 8);
            *(uint4*)&sA[r * SA_STRIDE + u * 8] = v;
        }
        // load B chunk: 64 rows x 64 k = 512 uint4, 2 per thread
        #pragma unroll
        for (int l = 0; l < 2; l++) {
            int fid = tid + l * 256;
            int r = fid >> 3;          // 0..63
            int u = fid & 7;
            uint4 v = *(const uint4*)(g_wt + (size_t)(col0 + r) * DMODEL + k0 + u * 8);
            *(uint4*)&sB[r * SB_STRIDE + u * 8] = v;
        }
        __syncthreads();
        #pragma unroll
        for (int ks = 0; ks < 4; ks++) {
            int kk = ks * 16;
            uint32_t a[2][4], b[4][2];
            #pragma unroll
            for (int mi = 0; mi < 2; mi++) {
                int ar = wm * 32 + mi * 16;
                const __nv_bfloat16* base = &sA[(ar + g) * SA_STRIDE + kk + 2 * tg];
                a[mi][0] = *(const uint32_t*)(base);
                a[mi][1] = *(const uint32_t*)(base + 8 * SA_STRIDE);
                a[mi][2] = *(const uint32_t*)(base + 8);
                a[mi][3] = *(const uint32_t*)(base + 8 * SA_STRIDE + 8);
            }
            #pragma unroll
            for (int ni = 0; ni < 4; ni++) {
                int bn = wn * 32 + ni * 8;
                const __nv_bfloat16* base = &sB[(bn + g) * SB_STRIDE + kk + 2 * tg];
                b[ni][0] = *(const uint32_t*)(base);
                b[ni][1] = *(const uint32_t*)(base + 8);
            }
            #pragma unroll
            for (int mi = 0; mi < 2; mi++)
                #pragma unroll
                for (int ni = 0; ni < 4; ni++)
                    mma16816(c[mi][ni], a[mi], b[ni]);
        }
        __syncthreads();
    }

    // epilogue: +bias, write fp32
    #pragma unroll
    for (int mi = 0; mi < 2; mi++) {
        int row = row0 + wm * 32 + mi * 16;
        #pragma unroll
        for (int ni = 0; ni < 4; ni++) {
            int col = col0 + wn * 32 + ni * 8 + 2 * tg;
            float2 bb = *(const float2*)&bias[768 + col];
            float2 r0, r1;
            r0.x = c[mi][ni][0] + bb.x; r0.y = c[mi][ni][1] + bb.y;
            r1.x = c[mi][ni][2] + bb.x; r1.y = c[mi][ni][3] + bb.y;
            *(float2*)&g_kv[(size_t)(row + g) * NKV + col] = r0;
            *(float2*)&g_kv[(size_t)(row + g + 8) * NKV + col] = r1;
        }
    }
}

// ============================================================================
// selection prob + y = x copy
// ============================================================================
__global__ void sel_copy_kernel(const float* __restrict__ x,
                                const float* __restrict__ sel_w,
                                const float* __restrict__ sel_b,
                                const float* __restrict__ temp,
                                float* __restrict__ y) {
    int r = blockIdx.x;
    const float* xr = x + (size_t)r * DMODEL;
    float* yr = y + (size_t)r * DMODEL;
    int tid = threadIdx.x;
    float p0 = 0.f, p1 = 0.f;
    #pragma unroll
    for (int j = tid; j < DMODEL; j += 256) {
        float v = xr[j];
        yr[j] = v;
        float2 w = *(const float2*)&sel_w[2*j];
        p0 = fmaf(v, w.x, p0);
        p1 = fmaf(v, w.y, p1);
    }
    #pragma unroll
    for (int off = 16; off; off >>= 1) {
        p0 += __shfl_down_sync(0xffffffffu, p0, off);
        p1 += __shfl_down_sync(0xffffffffu, p1, off);
    }
    __shared__ float s0[8], s1[8];
    int w = tid >> 5;
    if ((tid & 31) == 0) { s0[w] = p0; s1[w] = p1; }
    __syncthreads();
    if (tid == 0) {
        float a0 = 0.f, a1 = 0.f;
        #pragma unroll
        for (int i = 0; i < 8; i++) { a0 += s0[i]; a1 += s1[i]; }
        a0 += sel_b[0]; a1 += sel_b[1];
        float d = (a1 - a0) / temp[0];
        g_p1[r] = 1.0f / (1.0f + expf(-d));
    }
}

// ============================================================================
__global__ void topk_kernel() {
    int b = blockIdx.x;
    __shared__ float vals[SEQL];
    int tid = threadIdx.x;
    for (int j = tid; j < SEQL; j += 32) vals[j] = g_p1[b*SEQL + j];
    __syncwarp();
    for (int k = 0; k < KSEL; k++) {
        float bv = -1e30f; int bi = 1 << 30;
        for (int j = tid; j < SEQL; j += 32) {
            float v = vals[j];
            if (v > bv) { bv = v; bi = j; }
        }
        #pragma unroll
        for (int off = 16; off; off >>= 1) {
            float ov = __shfl_xor_sync(0xffffffffu, bv, off);
            int   oi = __shfl_xor_sync(0xffffffffu, bi, off);
            if (ov > bv || (ov == bv && oi < bi)) { bv = ov; bi = oi; }
        }
        if (tid == 0) {
            g_idx[b*KSEL + k] = bi;
            vals[bi] = -2e30f;
        }
        __syncwarp();
    }
}

// ============================================================================
__global__ void gather_kernel(const float* __restrict__ x) {
    int r = blockIdx.x;
    int tid = threadIdx.x;
    float* gq = g_q + (size_t)r * DMODEL;
    float* gx = g_xq + (size_t)r * DMODEL;
    if (r < NQ) {
        int b = r / KSEL;
        int t = g_idx[r];
        const float* xr = x + (size_t)(b*SEQL + t) * DMODEL;
        for (int j = tid; j < DMODEL; j += 256) { gx[j] = xr[j]; gq[j] = 0.f; }
    } else {
        for (int j = tid; j < DMODEL; j += 256) { gx[j] = 0.f; gq[j] = 0.f; }
    }
}

// ============================================================================
__global__ void __launch_bounds__(256) qproj_kernel(const float* __restrict__ W,
                                                    const float* __restrict__ bias) {
    __shared__ float As[64*48];
    __shared__ float Bs[64*64];
    int tid = threadIdx.x;
    int tx = tid & 15, ty = tid >> 4;
    int cb = blockIdx.x * 64;
    int rt = blockIdx.y;
    int kb = blockIdx.z * 64;

    #pragma unroll
    for (int l = 0; l < 3; l++) {
        int fid = tid + l*256;
        int row = fid >> 4;
        int kc  = (fid & 15) << 2;
        float4 v = *(const float4*)&g_xq[(size_t)(rt*48 + row)*DMODEL + kb + kc];
        As[(kc+0)*48 + row] = v.x; As[(kc+1)*48 + row] = v.y;
        As[(kc+2)*48 + row] = v.z; As[(kc+3)*48 + row] = v.w;
    }
    #pragma unroll
    for (int l = 0; l < 4; l++) {
        int fid = tid + l*256;
        int kr = fid >> 4;
        int c4 = (fid & 15) << 2;
        *(float4*)&Bs[kr*64 + c4] = *(const float4*)&W[(size_t)(kb + kr)*WQKV_COLS + cb + c4];
    }
    __syncthreads();
    float acc[3][4];
    #pragma unroll
    for (int i = 0; i < 3; i++)
        #pragma unroll
        for (int j = 0; j < 4; j++) acc[i][j] = 0.f;
    #pragma unroll 8
    for (int k = 0; k < 64; k++) {
        float4 bv = *(const float4*)&Bs[k*64 + tx*4];
        #pragma unroll
        for (int i = 0; i < 3; i++) {
            float a = As[k*48 + ty*3 + i];
            acc[i][0] = fmaf(a, bv.x, acc[i][0]);
            acc[i][1] = fmaf(a, bv.y, acc[i][1]);
            acc[i][2] = fmaf(a, bv.z, acc[i][2]);
            acc[i][3] = fmaf(a, bv.w, acc[i][3]);
        }
    }
    #pragma unroll
    for (int i = 0; i < 3; i++) {
        int row = rt*48 + ty*3 + i;
        if (row < NQ) {
            #pragma unroll
            for (int j = 0; j < 4; j++) {
                int col = cb + tx*4 + j;
                float v = acc[i][j] + (blockIdx.z == 0 ? bias[col] : 0.f);
                atomicAdd(&g_q[(size_t)row*DMODEL + col], v);
            }
        }
    }
}

// ============================================================================
__global__ void __launch_bounds__(256) attn_chunk_kernel() {
    int c  = blockIdx.x;
    int h  = blockIdx.y;
    int b  = blockIdx.z;
    int c0 = c * CH;
    int tid = threadIdx.x;
    int tx = tid & 15, ty = tid >> 4;

    __shared__ float qs[48*HD];
    __shared__ float kv_s[CH*HD];
    __shared__ float S[48*66];
    __shared__ int   ts[48];

    if (tid < 48) ts[tid] = (tid < KSEL) ? g_idx[b*KSEL + tid] : -1;
    for (int idx = tid; idx < 48*HD; idx += 256) {
        int q = idx >> 6, d = idx & 63;
        qs[idx] = (q < KSEL) ? g_q[(size_t)(b*KSEL + q)*DMODEL + h*HD + d] * 0.125f : 0.f;
    }
    const float* kvb = g_kv + (size_t)b * SEQL * NKV;
    #pragma unroll
    for (int l = 0; l < 4; l++) {
        int fid = tid + l*256;
        int key = fid >> 4;
        int dq  = (fid & 15) << 2;
        float4 v = *(const float4*)&kvb[(size_t)(c0 + key)*NKV + h*HD + dq];
        kv_s[(dq+0)*CH + key] = v.x; kv_s[(dq+1)*CH + key] = v.y;
        kv_s[(dq+2)*CH + key] = v.z; kv_s[(dq+3)*CH + key] = v.w;
    }
    __syncthreads();

    float acc[3][4];
    #pragma unroll
    for (int i = 0; i < 3; i++)
        #pragma unroll
        for (int j = 0; j < 4; j++) acc[i][j] = 0.f;
    #pragma unroll 8
    for (int d = 0; d < HD; d++) {
        float4 bv = *(const float4*)&kv_s[d*CH + tx*4];
        #pragma unroll
        for (int i = 0; i < 3; i++) {
            float a = qs[(ty*3+i)*HD + d];
            acc[i][0] = fmaf(a, bv.x, acc[i][0]);
            acc[i][1] = fmaf(a, bv.y, acc[i][1]);
            acc[i][2] = fmaf(a, bv.z, acc[i][2]);
            acc[i][3] = fmaf(a, bv.w, acc[i][3]);
        }
    }
    #pragma unroll
    for (int i = 0; i < 3; i++) {
        int q = ty*3 + i;
        int tq = ts[q];
        #pragma unroll
        for (int j = 0; j < 4; j++) {
            int sg = c0 + tx*4 + j;
            S[q*66 + tx*4 + j] = (q < KSEL && sg <= tq) ? acc[i][j] : -1e30f;
        }
    }
    __syncthreads();

    #pragma unroll
    for (int l = 0; l < 4; l++) {
        int fid = tid + l*256;
        int key = fid >> 4;
        int dq  = (fid & 15) << 2;
        *(float4*)&kv_s[key*HD + dq] =
            *(const float4*)&kvb[(size_t)(c0 + key)*NKV + DMODEL + h*HD + dq];
    }
    if (tid < 48) {
        int q = tid;
        float m = -1e30f;
        #pragma unroll 8
        for (int k = 0; k < CH; k++) m = fmaxf(m, S[q*66 + k]);
        float l = 0.f;
        #pragma unroll 8
        for (int k = 0; k < CH; k++) {
            float v = S[q*66 + k];
            float p = (v > -1e29f) ? __expf(v - m) : 0.f;
            S[q*66 + k] = p;
            l += p;
        }
        int base = ((b*NH + h)*NCH + c)*48 + q;
        g_pm[base] = m;
        g_pl[base] = l;
    }
    __syncthreads();

    float acc2[3][4];
    #pragma unroll
    for (int i = 0; i < 3; i++)
        #pragma unroll
        for (int j = 0; j < 4; j++) acc2[i][j] = 0.f;
    #pragma unroll 8
    for (int k = 0; k < CH; k++) {
        float4 bv = *(const float4*)&kv_s[k*HD + tx*4];
        #pragma unroll
        for (int i = 0; i < 3; i++) {
            float a = S[(ty*3+i)*66 + k];
            acc2[i][0] = fmaf(a, bv.x, acc2[i][0]);
            acc2[i][1] = fmaf(a, bv.y, acc2[i][1]);
            acc2[i][2] = fmaf(a, bv.z, acc2[i][2]);
            acc2[i][3] = fmaf(a, bv.w, acc2[i][3]);
        }
    }
    size_t obase = ((size_t)((b*NH + h)*NCH + c))*48;
    #pragma unroll
    for (int i = 0; i < 3; i++) {
        float4 r; r.x = acc2[i][0]; r.y = acc2[i][1]; r.z = acc2[i][2]; r.w = acc2[i][3];
        *(float4*)&g_po[(obase + ty*3 + i)*HD + tx*4] = r;
    }
}

// ============================================================================
__global__ void attn_combine_kernel() {
    int bx = blockIdx.x;
    int q  = bx / NH;
    int h  = bx % NH;
    int b  = q / KSEL;
    int qi = q % KSEL;
    int d  = threadIdx.x;
    int bh = b*NH + h;

    float m = -1e30f;
    #pragma unroll
    for (int c = 0; c < NCH; c++)
        m = fmaxf(m, g_pm[(bh*NCH + c)*48 + qi]);
    float num = 0.f, den = 0.f;
    #pragma unroll
    for (int c = 0; c < NCH; c++) {
        int base = (bh*NCH + c)*48 + qi;
        float w = __expf(g_pm[base] - m);
        den = fmaf(w, g_pl[base], den);
        num = fmaf(w, g_po[(size_t)base*HD + d], num);
    }
    g_ctx[(size_t)q*DMODEL + h*HD + d] = num / den;
}

// ============================================================================
__global__ void __launch_bounds__(256) outproj_kernel(const float* __restrict__ W,
                                                      const float* __restrict__ bias,
                                                      float* __restrict__ y) {
    __shared__ float As[64*48];
    __shared__ float Bs[64*64];
    int tid = threadIdx.x;
    int tx = tid & 15, ty = tid >> 4;
    int cb = blockIdx.x * 64;
    int rt = blockIdx.y;
    int kb = blockIdx.z * 64;

    #pragma unroll
    for (int l = 0; l < 3; l++) {
        int fid = tid + l*256;
        int row = fid >> 4;
        int kc  = (fid & 15) << 2;
        float4 v = *(const float4*)&g_ctx[(size_t)(rt*48 + row)*DMODEL + kb + kc];
        As[(kc+0)*48 + row] = v.x; As[(kc+1)*48 + row] = v.y;
        As[(kc+2)*48 + row] = v.z; As[(kc+3)*48 + row] = v.w;
    }
    #pragma unroll
    for (int l = 0; l < 4; l++) {
        int fid = tid + l*256;
        int kr = fid >> 4;
        int c4 = (fid & 15) << 2;
        *(float4*)&Bs[kr*64 + c4] = *(const float4*)&W[(size_t)(kb + kr)*DMODEL + cb + c4];
    }
    __syncthreads();
    float acc[3][4];
    #pragma unroll
    for (int i = 0; i < 3; i++)
        #pragma unroll
        for (int j = 0; j < 4; j++) acc[i][j] = 0.f;
    #pragma unroll 8
    for (int k = 0; k < 64; k++) {
        float4 bv = *(const float4*)&Bs[k*64 + tx*4];
        #pragma unroll
        for (int i = 0; i < 3; i++) {
            float a = As[k*48 + ty*3 + i];
            acc[i][0] = fmaf(a, bv.x, acc[i][0]);
            acc[i][1] = fmaf(a, bv.y, acc[i][1]);
            acc[i][2] = fmaf(a, bv.z, acc[i][2]);
            acc[i][3] = fmaf(a, bv.w, acc[i][3]);
        }
    }
    #pragma unroll
    for (int i = 0; i < 3; i++) {
        int row = rt*48 + ty*3 + i;
        if (row < NQ) {
            int b = row / KSEL;
            int t = g_idx[row];
            float p = g_p1[b*SEQL + t];
            float* yr = y + (size_t)(b*SEQL + t)*DMODEL;
            #pragma unroll
            for (int j = 0; j < 4; j++) {
                int col = cb + tx*4 + j;
                float v = acc[i][j] + (blockIdx.z == 0 ? bias[col] : 0.f);
                atomicAdd(&yr[col], p * v);
            }
        }
    }
}

// ============================================================================
extern "C" void kernel_launch(void* const* d_in, const int* in_sizes, int n_in,
                              void* d_out, int out_size) {
    const float* x     = (const float*)d_in[0];
    const float* Wqkv  = (const float*)d_in[1];
    const float* bqkv  = (const float*)d_in[2];
    const float* sel_w = (const float*)d_in[3];
    const float* sel_b = (const float*)d_in[4];
    const float* out_w = (const float*)d_in[5];
    const float* out_b = (const float*)d_in[6];
    const float* temp  = (const float*)d_in[7];
    float* y = (float*)d_out;

    x_convert_kernel<<<(NROWS*DMODEL)/(8*256), 256>>>(x);
    w_transpose_kernel<<<dim3(NKV/32, DMODEL/32), dim3(32, 8)>>>(Wqkv);
    sel_copy_kernel<<<NROWS, 256>>>(x, sel_w, sel_b, temp, y);
    kv_mma_kernel<<<dim3(NKV/64, NROWS/128), 256>>>(bqkv);
    topk_kernel<<<BATCH, 32>>>();
    gather_kernel<<<NQP, 256>>>(x);
    qproj_kernel<<<dim3(12, 2, 12), 256>>>(Wqkv, bqkv);
    attn_chunk_kernel<<<dim3(NCH, NH, BATCH), 256>>>();
    attn_combine_kernel<<<NQ*NH, HD>>>();
    outproj_kernel<<<dim3(12, 2, 12), 256>>>(out_w, out_b, y);
}